// round 2
// baseline (speedup 1.0000x reference)
#include <cuda_runtime.h>
#include <cuda_bf16.h>
#include <cstdint>
#include <math.h>

// ---------------------------------------------------------------------------
// BertAdapter: out = x + (gelu_new(LN(x) @ Wd + bd) @ Wu + bu)
// x: [32768, 1024] fp32.  Wd: [1024,256], Wu: [256,1024] fp32.
// PTX target is plain sm_103 (no tcgen05) -> use mma.sync m16n8k16 bf16 HMMA.
// ---------------------------------------------------------------------------

#define TOKENS   32768
#define HIDDEN   1024
#define ADAPTER  256

__device__ __nv_bfloat16 g_inter[TOKENS * ADAPTER];   // 16 MB intermediate
__device__ __nv_bfloat16 g_wdT[HIDDEN * ADAPTER];     // wdT[n*1024 + k] = wd[k][n]
__device__ __nv_bfloat16 g_wuT[ADAPTER * HIDDEN];     // wuT[n*256  + k] = wu[k][n]
__device__ float g_mean[TOKENS];
__device__ float g_rstd[TOKENS];

// ---------------- helpers ----------------
static __device__ __forceinline__ uint32_t smem_u32(const void* p) {
    uint32_t a;
    asm("{ .reg .u64 t; cvta.to.shared.u64 t, %1; cvt.u32.u64 %0, t; }"
        : "=r"(a) : "l"(p));
    return a;
}
static __device__ __forceinline__ uint32_t sw128(uint32_t o) {
    return o ^ ((o >> 3) & 0x70);
}

#define LDMATRIX_X4(r0, r1, r2, r3, addr)                                      \
    asm volatile("ldmatrix.sync.aligned.m8n8.x4.shared.b16 {%0,%1,%2,%3}, [%4];" \
                 : "=r"(r0), "=r"(r1), "=r"(r2), "=r"(r3) : "r"(addr))

#define MMA_BF16(d, a, bb0, bb1)                                               \
    asm volatile(                                                              \
        "mma.sync.aligned.m16n8k16.row.col.f32.bf16.bf16.f32 "                 \
        "{%0,%1,%2,%3}, {%4,%5,%6,%7}, {%8,%9}, {%0,%1,%2,%3};"                \
        : "+f"((d)[0]), "+f"((d)[1]), "+f"((d)[2]), "+f"((d)[3])               \
        : "r"((a)[0]), "r"((a)[1]), "r"((a)[2]), "r"((a)[3]),                  \
          "r"(bb0), "r"(bb1))

#define CP_ASYNC16(dst, src)                                                   \
    asm volatile("cp.async.cg.shared.global [%0], [%1], 16;"                   \
                 :: "r"(dst), "l"(src))
#define CP_COMMIT() asm volatile("cp.async.commit_group;" ::: "memory")
#define CP_WAIT0()  asm volatile("cp.async.wait_group 0;" ::: "memory")

static __device__ __forceinline__ float gelu_new_f(float x) {
    float x3 = x * x * x;
    float t = tanhf(0.7978845608028654f * (x + 0.044715f * x3));
    return 0.5f * x * (1.0f + t);
}

// smem layout (relative to 1024-aligned base):
//   0     : s_mu[128]   (gemm1 only)
//   512   : s_rs[128]
//   1024  : A buf0 (128 rows x 128B = 16KB)
//   17408 : A buf1
//   33792 : B buf0 (128 rows x 128B = 16KB)
//   50176 : B buf1
#define SMEM_A0 1024u
#define SMEM_A1 17408u
#define SMEM_B0 33792u
#define SMEM_B1 50176u
#define SMEM_BYTES (66560 + 1024)

// ---------------- prep: transpose + bf16 convert weights ----------------
__global__ void __launch_bounds__(256) prep_w(const float* __restrict__ wd,
                                              const float* __restrict__ wu) {
    int i = blockIdx.x * 256 + threadIdx.x;            // 262144 total
    int n = i >> 10, k = i & 1023;
    g_wdT[i] = __float2bfloat16(wd[k * ADAPTER + n]);
    int n2 = i >> 8, k2 = i & 255;
    g_wuT[i] = __float2bfloat16(wu[k2 * HIDDEN + n2]);
}

// ---------------- LN row statistics: one warp per row ----------------
__global__ void __launch_bounds__(256) ln_stats(const float* __restrict__ x) {
    int row = blockIdx.x * 8 + (threadIdx.x >> 5);
    int lid = threadIdx.x & 31;
    const float4* p = (const float4*)x + (size_t)row * 256;
    float s = 0.f, ss = 0.f;
#pragma unroll
    for (int i = 0; i < 8; i++) {
        float4 v = p[lid + i * 32];
        s  += v.x + v.y + v.z + v.w;
        ss += v.x * v.x + v.y * v.y + v.z * v.z + v.w * v.w;
    }
#pragma unroll
    for (int o = 16; o; o >>= 1) {
        s  += __shfl_xor_sync(0xFFFFFFFFu, s, o);
        ss += __shfl_xor_sync(0xFFFFFFFFu, ss, o);
    }
    if (lid == 0) {
        float mu = s * (1.0f / 1024.0f);
        float var = ss * (1.0f / 1024.0f) - mu * mu;
        g_mean[row] = mu;
        g_rstd[row] = rsqrtf(var + 1e-5f);
    }
}

// ---------------- shared compute core: 128x128 tile, 8 warps ----------------
// warp grid 4(m) x 2(n); warp tile 32x64; mma m16n8k16.
struct Frag { float acc[2][8][4]; };

static __device__ __forceinline__ void tile_compute(uint32_t ab, uint32_t bb,
                                                    int lid, int wm, int wn,
                                                    Frag& f) {
#pragma unroll
    for (int kk = 0; kk < 4; kk++) {
        uint32_t a[2][4];
#pragma unroll
        for (int mt = 0; mt < 2; mt++) {
            uint32_t off = (uint32_t)(wm + mt * 16 + (lid & 15)) * 128u +
                           (uint32_t)(kk * 32 + ((lid >> 4) << 4));
            LDMATRIX_X4(a[mt][0], a[mt][1], a[mt][2], a[mt][3], ab + sw128(off));
        }
        uint32_t b[4][4];
#pragma unroll
        for (int g = 0; g < 4; g++) {
            uint32_t row = (uint32_t)(wn + g * 16 + (lid & 7) + ((lid >> 4) << 3));
            uint32_t off = row * 128u +
                           (uint32_t)(kk * 32 + (((lid >> 3) & 1) << 4));
            LDMATRIX_X4(b[g][0], b[g][1], b[g][2], b[g][3], bb + sw128(off));
        }
#pragma unroll
        for (int mt = 0; mt < 2; mt++)
#pragma unroll
            for (int nt = 0; nt < 8; nt++) {
                int g = nt >> 1;
                if ((nt & 1) == 0) MMA_BF16(f.acc[mt][nt], a[mt], b[g][0], b[g][1]);
                else               MMA_BF16(f.acc[mt][nt], a[mt], b[g][2], b[g][3]);
            }
    }
}

// ---------------- GEMM1: LN(x) @ Wd -> gelu -> g_inter (bf16) ----------------
__global__ void __launch_bounds__(256)
gemm1_kernel(const float* __restrict__ x, const float* __restrict__ lnw,
             const float* __restrict__ lnb, const float* __restrict__ bdown) {
    extern __shared__ char smem_raw[];
    const int tid = threadIdx.x, wid = tid >> 5, lid = tid & 31;
    const int m0 = blockIdx.x * 128;
    const int n0 = blockIdx.y * 128;
    const int wm = (wid & 3) * 32, wn = (wid >> 2) * 64;

    uint32_t sb0 = smem_u32(smem_raw);
    uint32_t pad = (1024u - (sb0 & 1023u)) & 1023u;
    char* smem = smem_raw + pad;
    uint32_t sb = sb0 + pad;
    float* s_mu = (float*)(smem);
    float* s_rs = (float*)(smem + 512);

    if (tid < 128) { s_mu[tid] = g_mean[m0 + tid]; s_rs[tid] = g_rstd[m0 + tid]; }
    __syncthreads();

    const float4* x4 = (const float4*)x;
    const float4* w4 = (const float4*)lnw;
    const float4* b4 = (const float4*)lnb;
    const uint4* wt4 = (const uint4*)g_wdT;

    const int f4 = tid & 15;         // float4 col within 64-wide chunk
    const int mbase = tid >> 4;      // row base (stride 16)

    float4 va[8]; float4 wv, bv;

    auto loadA_regs = [&](int kt) {
        int k4 = kt * 16 + f4;
        wv = w4[k4]; bv = b4[k4];
#pragma unroll
        for (int i = 0; i < 8; i++)
            va[i] = x4[(size_t)(m0 + mbase + i * 16) * 256 + k4];
    };
    auto storeA = [&](uint32_t ab) {
#pragma unroll
        for (int i = 0; i < 8; i++) {
            int m = mbase + i * 16;
            float mu = s_mu[m], rs = s_rs[m];
            __nv_bfloat162 p0 = __floats2bfloat162_rn((va[i].x - mu) * rs * wv.x + bv.x,
                                                      (va[i].y - mu) * rs * wv.y + bv.y);
            __nv_bfloat162 p1 = __floats2bfloat162_rn((va[i].z - mu) * rs * wv.z + bv.z,
                                                      (va[i].w - mu) * rs * wv.w + bv.w);
            uint2 val;
            val.x = *(uint32_t*)&p0;
            val.y = *(uint32_t*)&p1;
            uint32_t off = (uint32_t)m * 128u + (uint32_t)f4 * 8u;
            *(uint2*)(smem + (ab - sb) + sw128(off)) = val;
        }
    };
    auto loadB_cp = [&](int kt, uint32_t bb) {
#pragma unroll
        for (int i = 0; i < 4; i++) {
            int idx = tid + i * 256;
            int n = idx >> 3, u = idx & 7;
            uint32_t dst = bb + sw128((uint32_t)n * 128u + (uint32_t)u * 16u);
            CP_ASYNC16(dst, &wt4[(size_t)(n0 + n) * 128 + kt * 8 + u]);
        }
        CP_COMMIT();
    };

    Frag f;
#pragma unroll
    for (int mt = 0; mt < 2; mt++)
#pragma unroll
        for (int nt = 0; nt < 8; nt++)
#pragma unroll
            for (int j = 0; j < 4; j++) f.acc[mt][nt][j] = 0.f;

    // prologue
    loadA_regs(0);
    loadB_cp(0, sb + SMEM_B0);
    storeA(sb + SMEM_A0);
    CP_WAIT0();
    __syncthreads();

#pragma unroll 1
    for (int kt = 0; kt < 16; kt++) {
        int buf = kt & 1;
        bool nxt = (kt + 1 < 16);
        if (nxt) {
            loadA_regs(kt + 1);
            loadB_cp(kt + 1, sb + (buf ? SMEM_B0 : SMEM_B1));
        }
        tile_compute(sb + (buf ? SMEM_A1 : SMEM_A0),
                     sb + (buf ? SMEM_B1 : SMEM_B0), lid, wm, wn, f);
        if (nxt) storeA(sb + (buf ? SMEM_A0 : SMEM_A1));
        CP_WAIT0();
        __syncthreads();
    }

    // epilogue: bias + gelu -> bf16 intermediate
    uint32_t* dst = (uint32_t*)g_inter;
#pragma unroll
    for (int mt = 0; mt < 2; mt++)
#pragma unroll
        for (int nt = 0; nt < 8; nt++) {
            int col = n0 + wn + nt * 8 + (lid & 3) * 2;
            int row = m0 + wm + mt * 16 + (lid >> 2);
            float b0 = bdown[col], b1 = bdown[col + 1];
            float* c = f.acc[mt][nt];
            __nv_bfloat162 p0 = __floats2bfloat162_rn(gelu_new_f(c[0] + b0),
                                                      gelu_new_f(c[1] + b1));
            __nv_bfloat162 p1 = __floats2bfloat162_rn(gelu_new_f(c[2] + b0),
                                                      gelu_new_f(c[3] + b1));
            dst[(size_t)row * 128 + col / 2]       = *(uint32_t*)&p0;
            dst[(size_t)(row + 8) * 128 + col / 2] = *(uint32_t*)&p1;
        }
}

// ---------------- GEMM2: g_inter @ Wu + bu + x -> out (fp32) ----------------
__global__ void __launch_bounds__(256)
gemm2_kernel(const float* __restrict__ x, const float* __restrict__ bup,
             float* __restrict__ out) {
    extern __shared__ char smem_raw[];
    const int tid = threadIdx.x, wid = tid >> 5, lid = tid & 31;
    const int m0 = blockIdx.x * 128;
    const int n0 = blockIdx.y * 128;
    const int wm = (wid & 3) * 32, wn = (wid >> 2) * 64;

    uint32_t sb0 = smem_u32(smem_raw);
    uint32_t pad = (1024u - (sb0 & 1023u)) & 1023u;
    uint32_t sb = sb0 + pad;

    const uint4* a4  = (const uint4*)g_inter;   // 32 uint4 per row
    const uint4* wt4 = (const uint4*)g_wuT;     // 32 uint4 per row

    auto load_cp = [&](int kt, uint32_t ab, uint32_t bb) {
#pragma unroll
        for (int i = 0; i < 4; i++) {
            int idx = tid + i * 256;
            int r = idx >> 3, u = idx & 7;
            uint32_t so = sw128((uint32_t)r * 128u + (uint32_t)u * 16u);
            CP_ASYNC16(ab + so, &a4[(size_t)(m0 + r) * 32 + kt * 8 + u]);
            CP_ASYNC16(bb + so, &wt4[(size_t)(n0 + r) * 32 + kt * 8 + u]);
        }
        CP_COMMIT();
    };

    Frag f;
#pragma unroll
    for (int mt = 0; mt < 2; mt++)
#pragma unroll
        for (int nt = 0; nt < 8; nt++)
#pragma unroll
            for (int j = 0; j < 4; j++) f.acc[mt][nt][j] = 0.f;

    load_cp(0, sb + SMEM_A0, sb + SMEM_B0);
    CP_WAIT0();
    __syncthreads();

#pragma unroll 1
    for (int kt = 0; kt < 4; kt++) {
        int buf = kt & 1;
        bool nxt = (kt + 1 < 4);
        if (nxt)
            load_cp(kt + 1, sb + (buf ? SMEM_A0 : SMEM_A1),
                    sb + (buf ? SMEM_B0 : SMEM_B1));
        tile_compute(sb + (buf ? SMEM_A1 : SMEM_A0),
                     sb + (buf ? SMEM_B1 : SMEM_B0), lid, wm, wn, f);
        CP_WAIT0();
        __syncthreads();
    }

    // epilogue: + bias + residual -> fp32 out
    const float2* x2 = (const float2*)x;
    const float2* bu2 = (const float2*)bup;
    float2* o2 = (float2*)out;
#pragma unroll
    for (int mt = 0; mt < 2; mt++)
#pragma unroll
        for (int nt = 0; nt < 8; nt++) {
            int col = n0 + wn + nt * 8 + (lid & 3) * 2;
            int row = m0 + wm + mt * 16 + (lid >> 2);
            float2 bv = bu2[col / 2];
            float* c = f.acc[mt][nt];
            float2 r0 = x2[(size_t)row * 512 + col / 2];
            float2 r1 = x2[(size_t)(row + 8) * 512 + col / 2];
            float2 o0, o1;
            o0.x = c[0] + bv.x + r0.x;  o0.y = c[1] + bv.y + r0.y;
            o1.x = c[2] + bv.x + r1.x;  o1.y = c[3] + bv.y + r1.y;
            o2[(size_t)row * 512 + col / 2]       = o0;
            o2[(size_t)(row + 8) * 512 + col / 2] = o1;
        }
}

// ---------------- host launcher ----------------
extern "C" void kernel_launch(void* const* d_in, const int* in_sizes, int n_in,
                              void* d_out, int out_size) {
    const float* x   = (const float*)d_in[0];
    const float* lnw = (const float*)d_in[1];
    const float* lnb = (const float*)d_in[2];
    const float* wd  = (const float*)d_in[3];
    const float* bd  = (const float*)d_in[4];
    const float* wu  = (const float*)d_in[5];
    const float* bu  = (const float*)d_in[6];
    float* out = (float*)d_out;

    cudaFuncSetAttribute(gemm1_kernel, cudaFuncAttributeMaxDynamicSharedMemorySize,
                         SMEM_BYTES);
    cudaFuncSetAttribute(gemm2_kernel, cudaFuncAttributeMaxDynamicSharedMemorySize,
                         SMEM_BYTES);

    prep_w<<<1024, 256>>>(wd, wu);
    ln_stats<<<4096, 256>>>(x);
    gemm1_kernel<<<dim3(256, 2), 256, SMEM_BYTES>>>(x, lnw, lnb, bd);
    gemm2_kernel<<<dim3(256, 8), 256, SMEM_BYTES>>>(x, bu, out);
    (void)in_sizes; (void)n_in; (void)out_size;
}

// round 3
// speedup vs baseline: 1.1293x; 1.1293x over previous
#include <cuda_runtime.h>
#include <cuda_bf16.h>
#include <cstdint>
#include <math.h>

// ---------------------------------------------------------------------------
// BertAdapter fused: out = x + (gelu_new(LN(x) @ Wd + bd) @ Wu + bu)
// Single kernel per 128-row tile: stats -> GEMM1(K=1024) -> GELU -> P in smem
// -> GEMM2 (K=256, N=1024 in 8 chunks) -> +bias +residual -> out.
// mma.sync m16n8k16 bf16 (PTX target is plain sm_103: no tcgen05).
// ---------------------------------------------------------------------------

#define TOKENS   32768
#define HIDDEN   1024
#define ADAPTER  256

__device__ __nv_bfloat16 g_wdT[HIDDEN * ADAPTER];   // wdT[n*1024 + k] = wd[k][n]
__device__ __nv_bfloat16 g_wuT[ADAPTER * HIDDEN];   // wuT[n*256  + k] = wu[k][n]

// ---------------- helpers ----------------
static __device__ __forceinline__ uint32_t smem_u32(const void* p) {
    uint32_t a;
    asm("{ .reg .u64 t; cvta.to.shared.u64 t, %1; cvt.u32.u64 %0, t; }"
        : "=r"(a) : "l"(p));
    return a;
}
static __device__ __forceinline__ uint32_t sw128(uint32_t o) {
    return o ^ ((o >> 3) & 0x70);
}

#define LDMATRIX_X4(r0, r1, r2, r3, addr)                                      \
    asm volatile("ldmatrix.sync.aligned.m8n8.x4.shared.b16 {%0,%1,%2,%3}, [%4];" \
                 : "=r"(r0), "=r"(r1), "=r"(r2), "=r"(r3) : "r"(addr))

#define MMA_BF16(d, a, bb0, bb1)                                               \
    asm volatile(                                                              \
        "mma.sync.aligned.m16n8k16.row.col.f32.bf16.bf16.f32 "                 \
        "{%0,%1,%2,%3}, {%4,%5,%6,%7}, {%8,%9}, {%0,%1,%2,%3};"                \
        : "+f"((d)[0]), "+f"((d)[1]), "+f"((d)[2]), "+f"((d)[3])               \
        : "r"((a)[0]), "r"((a)[1]), "r"((a)[2]), "r"((a)[3]),                  \
          "r"(bb0), "r"(bb1))

#define CP_ASYNC16(dst, src)                                                   \
    asm volatile("cp.async.cg.shared.global [%0], [%1], 16;"                   \
                 :: "r"(dst), "l"(src))
#define CP_COMMIT() asm volatile("cp.async.commit_group;" ::: "memory")
#define CP_WAIT0()  asm volatile("cp.async.wait_group 0;" ::: "memory")

static __device__ __forceinline__ float gelu_new_f(float x) {
    float x3 = x * x * x;
    float t = tanhf(0.7978845608028654f * (x + 0.044715f * x3));
    return 0.5f * x * (1.0f + t);
}

// smem map (relative to 1024-aligned base):
//   0      : s_mu[128]
//   512    : s_rs[128]
//   1024   : P panels: 4 x (128 rows x 128B)  = 64KB   [1024, 66560)
//   66560  : G1 A buf0/1: 2 x 16KB                     [66560, 99328)
//   99328  : G1 B buf0/1: 2 x 32KB                     [99328, 164864)
//   66560  : G2 B buf0 (aliases G1A+G1B0): 64KB        [66560, 132096)
//   132096 : G2 B buf1: 64KB                           [132096, 197632)
#define S_P     1024u
#define S_G1A0  66560u
#define S_G1A1  82944u
#define S_G1B0  99328u
#define S_G1B1  132096u
#define S_G2B0  66560u
#define S_G2B1  132096u
#define SMEM_BYTES (197632 + 1024)

// ---------------- prep: transpose + bf16 convert weights ----------------
__global__ void __launch_bounds__(256) prep_w(const float* __restrict__ wd,
                                              const float* __restrict__ wu) {
    int i = blockIdx.x * 256 + threadIdx.x;            // 262144 total
    int n = i >> 10, k = i & 1023;
    g_wdT[i] = __float2bfloat16(wd[k * ADAPTER + n]);
    int n2 = i >> 8, k2 = i & 255;
    g_wuT[i] = __float2bfloat16(wu[k2 * HIDDEN + n2]);
}

// ---------------- fragment holders ----------------
struct Frag64 { float a[2][8][4]; };   // warp tile 32x64
struct Frag32 { float a[2][4][4]; };   // warp tile 32x32

// A from [128 x 64] panel (rows 128B, SW128), B from [rows x 64] panel.
static __device__ __forceinline__ void tile_compute64(uint32_t ab, uint32_t bb,
                                                      int lid, int wm, int wn,
                                                      Frag64& f) {
#pragma unroll
    for (int kk = 0; kk < 4; kk++) {
        uint32_t a[2][4];
#pragma unroll
        for (int mt = 0; mt < 2; mt++) {
            uint32_t off = (uint32_t)(wm + mt * 16 + (lid & 15)) * 128u +
                           (uint32_t)(kk * 32 + ((lid >> 4) << 4));
            LDMATRIX_X4(a[mt][0], a[mt][1], a[mt][2], a[mt][3], ab + sw128(off));
        }
        uint32_t b[4][4];
#pragma unroll
        for (int g = 0; g < 4; g++) {
            uint32_t row = (uint32_t)(wn + g * 16 + (lid & 7) + ((lid >> 4) << 3));
            uint32_t off = row * 128u +
                           (uint32_t)(kk * 32 + (((lid >> 3) & 1) << 4));
            LDMATRIX_X4(b[g][0], b[g][1], b[g][2], b[g][3], bb + sw128(off));
        }
#pragma unroll
        for (int mt = 0; mt < 2; mt++)
#pragma unroll
            for (int nt = 0; nt < 8; nt++) {
                int g = nt >> 1;
                if ((nt & 1) == 0) MMA_BF16(f.a[mt][nt], a[mt], b[g][0], b[g][1]);
                else               MMA_BF16(f.a[mt][nt], a[mt], b[g][2], b[g][3]);
            }
    }
}

static __device__ __forceinline__ void tile_compute32(uint32_t ab, uint32_t bb,
                                                      int lid, int wm, int wn,
                                                      Frag32& f) {
#pragma unroll
    for (int kk = 0; kk < 4; kk++) {
        uint32_t a[2][4];
#pragma unroll
        for (int mt = 0; mt < 2; mt++) {
            uint32_t off = (uint32_t)(wm + mt * 16 + (lid & 15)) * 128u +
                           (uint32_t)(kk * 32 + ((lid >> 4) << 4));
            LDMATRIX_X4(a[mt][0], a[mt][1], a[mt][2], a[mt][3], ab + sw128(off));
        }
        uint32_t b[2][4];
#pragma unroll
        for (int g = 0; g < 2; g++) {
            uint32_t row = (uint32_t)(wn + g * 16 + (lid & 7) + ((lid >> 4) << 3));
            uint32_t off = row * 128u +
                           (uint32_t)(kk * 32 + (((lid >> 3) & 1) << 4));
            LDMATRIX_X4(b[g][0], b[g][1], b[g][2], b[g][3], bb + sw128(off));
        }
#pragma unroll
        for (int mt = 0; mt < 2; mt++)
#pragma unroll
            for (int nt = 0; nt < 4; nt++) {
                int g = nt >> 1;
                if ((nt & 1) == 0) MMA_BF16(f.a[mt][nt], a[mt], b[g][0], b[g][1]);
                else               MMA_BF16(f.a[mt][nt], a[mt], b[g][2], b[g][3]);
            }
    }
}

// ---------------- the fused kernel ----------------
__global__ void __launch_bounds__(512)
fused_kernel(const float* __restrict__ x, const float* __restrict__ lnw,
             const float* __restrict__ lnb, const float* __restrict__ bdown,
             const float* __restrict__ bup, float* __restrict__ out) {
    extern __shared__ char smem_raw[];
    const int tid = threadIdx.x, wid = tid >> 5, lid = tid & 31;
    const int m0 = blockIdx.x * 128;

    uint32_t sb0 = smem_u32(smem_raw);
    uint32_t pad = (1024u - (sb0 & 1023u)) & 1023u;
    char* smem = smem_raw + pad;
    uint32_t sb = sb0 + pad;
    float* s_mu = (float*)smem;
    float* s_rs = (float*)(smem + 512);

    const float4* x4 = (const float4*)x;

    // ================= phase 0: LN stats (warp per row, 8 rows/warp) ======
#pragma unroll 1
    for (int r8 = 0; r8 < 8; r8++) {
        int row = wid * 8 + r8;
        const float4* p = x4 + (size_t)(m0 + row) * 256;
        float s = 0.f, ss = 0.f;
#pragma unroll
        for (int i = 0; i < 8; i++) {
            float4 v = p[lid + i * 32];
            s  += v.x + v.y + v.z + v.w;
            ss += v.x * v.x + v.y * v.y + v.z * v.z + v.w * v.w;
        }
#pragma unroll
        for (int o = 16; o; o >>= 1) {
            s  += __shfl_xor_sync(0xFFFFFFFFu, s, o);
            ss += __shfl_xor_sync(0xFFFFFFFFu, ss, o);
        }
        if (lid == 0) {
            float mu = s * (1.0f / 1024.0f);
            float var = ss * (1.0f / 1024.0f) - mu * mu;
            s_mu[row] = mu;
            s_rs[row] = rsqrtf(var + 1e-5f);
        }
    }
    __syncthreads();

    // ================= phase 1: GEMM1 (128x256, K=1024) ===================
    const int wm1 = (wid & 3) * 32, wn1 = (wid >> 2) * 64;
    const float4* w4 = (const float4*)lnw;
    const float4* b4 = (const float4*)lnb;
    const uint4* wdT4 = (const uint4*)g_wdT;
    const uint4* wuT4 = (const uint4*)g_wuT;

    const int f4 = tid & 15;       // float4 col within 64-wide k-chunk
    const int mb = tid >> 4;       // 0..31, rows mb + i*32

    auto loadB2 = [&](int nc, uint32_t bbuf) {  // gemm2 Wu chunk: 128 rows x 256k
#pragma unroll
        for (int i = 0; i < 8; i++) {
            int idx = tid + i * 512;
            int r = idx >> 5, u = idx & 31;
            int p = u >> 3, u8 = u & 7;
            uint32_t dst = bbuf + (uint32_t)p * 16384u +
                           sw128((uint32_t)r * 128u + (uint32_t)u8 * 16u);
            CP_ASYNC16(dst, &wuT4[(size_t)(nc * 128 + r) * 32 + u]);
        }
        CP_COMMIT();
    };

    {
        float4 va[4]; float4 wv, bv;
        auto loadA_regs = [&](int kt) {
            int k4 = kt * 16 + f4;
            wv = w4[k4]; bv = b4[k4];
#pragma unroll
            for (int i = 0; i < 4; i++)
                va[i] = x4[(size_t)(m0 + mb + i * 32) * 256 + k4];
        };
        auto storeA = [&](uint32_t aoff) {
#pragma unroll
            for (int i = 0; i < 4; i++) {
                int m = mb + i * 32;
                float mu = s_mu[m], rs = s_rs[m];
                __nv_bfloat162 p0 = __floats2bfloat162_rn(
                    (va[i].x - mu) * rs * wv.x + bv.x,
                    (va[i].y - mu) * rs * wv.y + bv.y);
                __nv_bfloat162 p1 = __floats2bfloat162_rn(
                    (va[i].z - mu) * rs * wv.z + bv.z,
                    (va[i].w - mu) * rs * wv.w + bv.w);
                uint2 val;
                val.x = *(uint32_t*)&p0;
                val.y = *(uint32_t*)&p1;
                *(uint2*)(smem + aoff + sw128((uint32_t)m * 128u + (uint32_t)f4 * 8u)) = val;
            }
        };
        auto loadB1 = [&](int kt, uint32_t bbuf) {  // 256 rows x 64 k
#pragma unroll
            for (int i = 0; i < 4; i++) {
                int idx = tid + i * 512;
                int n = idx >> 3, u = idx & 7;
                uint32_t dst = bbuf + sw128((uint32_t)n * 128u + (uint32_t)u * 16u);
                CP_ASYNC16(dst, &wdT4[(size_t)n * 128 + kt * 8 + u]);
            }
            CP_COMMIT();
        };

        Frag64 f1;
#pragma unroll
        for (int mt = 0; mt < 2; mt++)
#pragma unroll
            for (int nt = 0; nt < 8; nt++)
#pragma unroll
                for (int j = 0; j < 4; j++) f1.a[mt][nt][j] = 0.f;

        loadA_regs(0);
        loadB1(0, sb + S_G1B0);
        storeA(S_G1A0);
        CP_WAIT0();
        __syncthreads();

#pragma unroll 1
        for (int kt = 0; kt < 16; kt++) {
            int buf = kt & 1;
            bool nxt = (kt + 1 < 16);
            if (nxt) {
                loadA_regs(kt + 1);
                loadB1(kt + 1, sb + (buf ? S_G1B0 : S_G1B1));
            }
            tile_compute64(sb + (buf ? S_G1A1 : S_G1A0),
                           sb + (buf ? S_G1B1 : S_G1B0), lid, wm1, wn1, f1);
            if (nxt) storeA(buf ? S_G1A0 : S_G1A1);
            CP_WAIT0();
            __syncthreads();
        }

        // prefetch GEMM2 B chunk 0 (buffers free after the sync above)
        loadB2(0, sb + S_G2B0);

        // GELU epilogue -> P panels in smem
#pragma unroll
        for (int mt = 0; mt < 2; mt++)
#pragma unroll
            for (int nt = 0; nt < 8; nt++) {
                int col = wn1 + nt * 8 + (lid & 3) * 2;
                int row = wm1 + mt * 16 + (lid >> 2);
                float b0 = bdown[col], b1 = bdown[col + 1];
                float* c = f1.a[mt][nt];
                __nv_bfloat162 p0 = __floats2bfloat162_rn(gelu_new_f(c[0] + b0),
                                                          gelu_new_f(c[1] + b1));
                __nv_bfloat162 p1 = __floats2bfloat162_rn(gelu_new_f(c[2] + b0),
                                                          gelu_new_f(c[3] + b1));
                uint32_t pan = (uint32_t)(col >> 6) * 16384u;
                uint32_t cin = (uint32_t)(col & 63) * 2u;
                *(uint32_t*)(smem + (S_P + pan) +
                             sw128((uint32_t)row * 128u + cin)) = *(uint32_t*)&p0;
                *(uint32_t*)(smem + (S_P + pan) +
                             sw128((uint32_t)(row + 8) * 128u + cin)) = *(uint32_t*)&p1;
            }
    }
    __syncthreads();   // P visible to all

    // ================= phase 2: GEMM2 (128x1024, K=256, 8 n-chunks) =======
    const int wm2 = (wid & 3) * 32, wn2 = (wid >> 2) * 32;
    const float2* x2  = (const float2*)x;
    const float2* bu2 = (const float2*)bup;
    float2* o2 = (float2*)out;

#pragma unroll 1
    for (int nc = 0; nc < 8; nc++) {
        CP_WAIT0();
        __syncthreads();
        int buf = nc & 1;
        if (nc + 1 < 8) loadB2(nc + 1, sb + (buf ? S_G2B0 : S_G2B1));

        Frag32 f2;
#pragma unroll
        for (int mt = 0; mt < 2; mt++)
#pragma unroll
            for (int nt = 0; nt < 4; nt++)
#pragma unroll
                for (int j = 0; j < 4; j++) f2.a[mt][nt][j] = 0.f;

        uint32_t bbase = sb + (buf ? S_G2B1 : S_G2B0);
#pragma unroll
        for (int p = 0; p < 4; p++)
            tile_compute32(sb + S_P + p * 16384u, bbase + p * 16384u,
                           lid, wm2, wn2, f2);

        // epilogue: + bias + residual -> out
#pragma unroll
        for (int mt = 0; mt < 2; mt++)
#pragma unroll
            for (int nt = 0; nt < 4; nt++) {
                int col = nc * 128 + wn2 + nt * 8 + (lid & 3) * 2;
                int row = m0 + wm2 + mt * 16 + (lid >> 2);
                float2 bv = bu2[col >> 1];
                float* c = f2.a[mt][nt];
                float2 r0 = x2[(size_t)row * 512 + (col >> 1)];
                float2 r1 = x2[(size_t)(row + 8) * 512 + (col >> 1)];
                float2 o0, o1;
                o0.x = c[0] + bv.x + r0.x;  o0.y = c[1] + bv.y + r0.y;
                o1.x = c[2] + bv.x + r1.x;  o1.y = c[3] + bv.y + r1.y;
                o2[(size_t)row * 512 + (col >> 1)]       = o0;
                o2[(size_t)(row + 8) * 512 + (col >> 1)] = o1;
            }
    }
}

// ---------------- host launcher ----------------
extern "C" void kernel_launch(void* const* d_in, const int* in_sizes, int n_in,
                              void* d_out, int out_size) {
    const float* x   = (const float*)d_in[0];
    const float* lnw = (const float*)d_in[1];
    const float* lnb = (const float*)d_in[2];
    const float* wd  = (const float*)d_in[3];
    const float* bd  = (const float*)d_in[4];
    const float* wu  = (const float*)d_in[5];
    const float* bu  = (const float*)d_in[6];
    float* out = (float*)d_out;

    cudaFuncSetAttribute(fused_kernel, cudaFuncAttributeMaxDynamicSharedMemorySize,
                         SMEM_BYTES);

    prep_w<<<1024, 256>>>(wd, wu);
    fused_kernel<<<256, 512, SMEM_BYTES>>>(x, lnw, lnb, bd, bu, out);
    (void)in_sizes; (void)n_in; (void)out_size;
}